// round 12
// baseline (speedup 1.0000x reference)
#include <cuda_runtime.h>
#include <stdint.h>
#include <math.h>

#define NB    16384
#define NPRE  1024
#define NPOST 512
#define BATCH 2
#define EPSI  1e-8f
#define THR   0.8f
#define NCAND 4096
#define NBINS 16384
#define MAXP  16384

// ---- scratch (no device allocation allowed). Every persistent mutable is
// restored by its consumer so graph replays see a clean slate. ----
__device__ int                g_topidx[BATCH * NPRE];
__device__ unsigned int       g_key32[BATCH * NB];      // desc-monotone score bits
__device__ unsigned int       g_hist[BATCH * NBINS];    // zeroed by kB after read
__device__ unsigned int       g_cum[BATCH * NBINS];     // rewritten by kB each run
__device__ unsigned int       g_bc[BATCH * NBINS];      // bin arrival cnt; zeroed by kD
__device__ int                g_bstar[BATCH];
__device__ int                g_cnt[BATCH];             // zeroed by kB (pre-kC)
__device__ __align__(16) unsigned long long g_cand[BATCH * NCAND];
__device__ float4             g_bevA[BATCH * NPRE];     // {x, y, radius, area}
__device__ float4             g_bevB[BATCH * NPRE];     // {dx, dy, cos, sin}
__device__ unsigned int       g_pairs[BATCH * MAXP];    // (i<<10)|j overlap pairs
__device__ int                g_pcnt[BATCH];            // zeroed by k_nms after read

// monotone descending transform: higher score -> smaller u32
__device__ __forceinline__ unsigned desc_bits(float s) {
    unsigned u = __float_as_uint(s);
    unsigned asc = (u & 0x80000000u) ? ~u : (u | 0x80000000u);
    return ~asc;
}

// ---------------------------------------------------------------------------
// kA: keys + 14-bit histogram. 4 boxes/thread via float4 loads. 32 blocks.
// ---------------------------------------------------------------------------
__global__ void __launch_bounds__(256) kA(const float* __restrict__ cls) {
    int t4 = blockIdx.x * 256 + threadIdx.x;      // [0, BATCH*NB/4)
    const float4* c4 = (const float4*)cls;
    float4 f0 = c4[t4 * 3 + 0];
    float4 f1 = c4[t4 * 3 + 1];
    float4 f2 = c4[t4 * 3 + 2];
    uint4 k;
    k.x = desc_bits(fmaxf(f0.x, fmaxf(f0.y, f0.z)));
    k.y = desc_bits(fmaxf(f0.w, fmaxf(f1.x, f1.y)));
    k.z = desc_bits(fmaxf(f1.z, fmaxf(f1.w, f2.x)));
    k.w = desc_bits(fmaxf(f2.y, fmaxf(f2.z, f2.w)));
    ((uint4*)g_key32)[t4] = k;
    unsigned int* hist = g_hist + (t4 >> 12) * NBINS;   // batch = t4*4 >> 14
    atomicAdd(&hist[k.x >> 18], 1u);
    atomicAdd(&hist[k.y >> 18], 1u);
    atomicAdd(&hist[k.z >> 18], 1u);
    atomicAdd(&hist[k.w >> 18], 1u);
}

// ---------------------------------------------------------------------------
// kB: per-batch scan of 16384 bins -> b* + exclusive prefix per bin (g_cum).
// Zeroes hist bins after reading; zeroes g_cnt.
// ---------------------------------------------------------------------------
__global__ void __launch_bounds__(1024) kB() {
    __shared__ unsigned int warpsum[32];
    int b = blockIdx.x;
    int tid = threadIdx.x;
    int lane = tid & 31, wid = tid >> 5;

    unsigned int* hist = g_hist + b * NBINS;
    unsigned int* cum  = g_cum  + b * NBINS;
    unsigned loc[16];
    unsigned s16 = 0;
    #pragma unroll
    for (int k = 0; k < 16; k++) { loc[k] = hist[tid * 16 + k]; s16 += loc[k]; }
    #pragma unroll
    for (int k = 0; k < 16; k++) hist[tid * 16 + k] = 0u;   // restore

    unsigned p = s16;
    #pragma unroll
    for (int off = 1; off < 32; off <<= 1) {
        unsigned v = __shfl_up_sync(0xffffffffu, p, off);
        if (lane >= off) p += v;
    }
    if (lane == 31) warpsum[wid] = p;
    __syncthreads();
    if (tid < 32) {
        unsigned q = warpsum[tid];
        #pragma unroll
        for (int off = 1; off < 32; off <<= 1) {
            unsigned v = __shfl_up_sync(0xffffffffu, q, off);
            if (tid >= off) q += v;
        }
        warpsum[tid] = q;
    }
    __syncthreads();
    unsigned run = (wid > 0 ? warpsum[wid - 1] : 0u) + p - s16;

    #pragma unroll
    for (int k = 0; k < 16; k++) {
        cum[tid * 16 + k] = run;
        if (run < NPRE && run + loc[k] >= NPRE) g_bstar[b] = tid * 16 + k;
        run += loc[k];
    }
    if (tid == 0) g_cnt[b] = 0;
}

// ---------------------------------------------------------------------------
// kC: place candidates (bin <= b*) directly at bin-sorted slots. 32 blocks.
// ---------------------------------------------------------------------------
__global__ void __launch_bounds__(256) kC() {
    int t4 = blockIdx.x * 256 + threadIdx.x;      // [0, BATCH*NB/4)
    int b = t4 >> 12;
    int bs = g_bstar[b];
    uint4 k = ((const uint4*)g_key32)[t4];
    unsigned base_idx = (unsigned)((t4 * 4) & (NB - 1));
    #pragma unroll
    for (int c = 0; c < 4; c++) {
        unsigned d = (c == 0) ? k.x : (c == 1) ? k.y : (c == 2) ? k.z : k.w;
        int bin = (int)(d >> 18);
        if (bin <= bs) {
            unsigned base = g_cum[b * NBINS + bin];
            unsigned pos  = atomicAdd(&g_bc[b * NBINS + bin], 1u);
            unsigned slot = base + pos;
            if (slot < NCAND)
                g_cand[b * NCAND + slot] =
                    (((unsigned long long)d) << 32) | (base_idx + c);
            atomicAdd(&g_cnt[b], 1);
        }
    }
}

// ---------------------------------------------------------------------------
// kD: rank = bin prefix + within-bin count (bin-mates are contiguous).
// Scatters top-1024 with bev precompute. Zeroes g_bc for touched bins.
// ---------------------------------------------------------------------------
__global__ void __launch_bounds__(256) kD(const float* __restrict__ box) {
    extern __shared__ unsigned long long sh[];    // up to NCAND u64 (32KB)
    int b = blockIdx.y;
    int tid = threadIdx.x;
    int C = g_cnt[b];
    if (C > NCAND) C = NCAND;
    if (blockIdx.x * 256 >= C) return;

    // vectorized staging: 2 u64 per 16B load
    const uint4* cand4 = (const uint4*)(g_cand + b * NCAND);
    int C2 = (C + 1) >> 1;
    for (int i = tid; i < C2; i += 256) ((uint4*)sh)[i] = cand4[i];
    __syncthreads();

    int me = blockIdx.x * 256 + tid;
    if (me >= C) return;
    unsigned long long my = sh[me];
    int mybin = (int)(my >> 50);

    g_bc[b * NBINS + mybin] = 0u;                 // restore (write-only, no race)

    int rank = (int)g_cum[b * NBINS + mybin];
    for (int s = rank; s < C; s++) {              // bin-mates start at prefix
        unsigned long long k2 = sh[s];
        if ((int)(k2 >> 50) != mybin) break;
        rank += (k2 < my);
    }

    if (rank < NPRE) {
        int idx = (int)(my & 0xffffffffu);
        g_topidx[b * NPRE + rank] = idx;
        const float* bp = box + ((size_t)b * NB + idx) * 7;
        float x = bp[0], y = bp[1], dx = bp[3], dy = bp[4], ry = bp[6];
        float r = 0.5f * sqrtf(dx * dx + dy * dy);
        g_bevA[b * NPRE + rank] = make_float4(x, y, r, dx * dy);
        g_bevB[b * NPRE + rank] = make_float4(dx, dy, cosf(ry), sinf(ry));
    }
}

// ---------------------------------------------------------------------------
// k_iou: quad-j mapping — each thread owns cell (i, jquad q) AND its mirror
// (1023-i, 255-q); the involution covers every cell exactly once. 4x fewer
// threads, A-load and index math amortized over 4 pairs. Survivors run the
// exact reference polygon algorithm and append to the pair list.
// ---------------------------------------------------------------------------
__global__ void __launch_bounds__(256) k_iou() {
    int t = blockIdx.x * 256 + threadIdx.x;   // [0, 512*256)
    int b = blockIdx.y;
    int i0 = t >> 8;                          // [0, 512)
    int q0 = t & 255;                         // [0, 256)

    #pragma unroll 1
    for (int c = 0; c < 2; c++) {
        int I = c ? (NPRE - 1 - i0) : i0;
        int Q = c ? (255 - q0) : q0;
        if (4 * Q + 3 <= I) continue;         // cell entirely in lower triangle

        float4 A4 = g_bevA[b * NPRE + I];
        float ax0 = A4.x, ay0 = A4.y;

        #pragma unroll 1
        for (int jj = 0; jj < 4; jj++) {
            int j = 4 * Q + jj;
            if (j <= I) continue;

            float4 B4 = g_bevA[b * NPRE + j];

            // reject 1: enclosing circles disjoint -> inter = 0
            float ddx = B4.x - ax0, ddy = B4.y - ay0;
            float rr = A4.z + B4.z;
            if (ddx * ddx + ddy * ddy > rr * rr) continue;

            // reject 2: iou <= min(area)/max(area)
            float Aa = A4.w, Ab = B4.w;
            float mn = fminf(Aa, Ab), mx = fmaxf(Aa, Ab);
            if (mn <= 0.79f * mx) continue;

            float4 Ad = g_bevB[b * NPRE + I];
            float4 Bd = g_bevB[b * NPRE + j];
            float adx = Ad.x, ady = Ad.y, acr = Ad.z, asr = Ad.w;
            float bx0 = B4.x, by0 = B4.y;
            float bdx = Bd.x, bdy = Bd.y, bcr = Bd.z, bsr = Bd.w;

            // ---- full reference algorithm ----
            const float offx[4] = { 0.5f, -0.5f, -0.5f,  0.5f };
            const float offy[4] = { 0.5f,  0.5f, -0.5f, -0.5f };

            float ax[4], ay[4], bx[4], by[4];
            #pragma unroll
            for (int k = 0; k < 4; k++) {
                float lx = adx * offx[k], ly = ady * offy[k];
                ax[k] = ax0 + lx * acr - ly * asr;
                ay[k] = ay0 + lx * asr + ly * acr;
                lx = bdx * offx[k]; ly = bdy * offy[k];
                bx[k] = bx0 + lx * bcr - ly * bsr;
                by[k] = by0 + lx * bsr + ly * bcr;
            }
            float dax[4], day[4], dbx[4], dby[4];
            #pragma unroll
            for (int k = 0; k < 4; k++) {
                dax[k] = ax[(k + 1) & 3] - ax[k];
                day[k] = ay[(k + 1) & 3] - ay[k];
                dbx[k] = bx[(k + 1) & 3] - bx[k];
                dby[k] = by[(k + 1) & 3] - by[k];
            }

            float px[24], py[24];
            bool  mk[24];
            #pragma unroll
            for (int ia = 0; ia < 4; ia++) {
                #pragma unroll
                for (int jb = 0; jb < 4; jb++) {
                    int id = ia * 4 + jb;
                    float den = dax[ia] * dby[jb] - day[ia] * dbx[jb];
                    float dx = bx[jb] - ax[ia], dy = by[jb] - ay[ia];
                    float dens = (fabsf(den) > EPSI) ? den : 1.0f;
                    float tt = (dx * dby[jb] - dy * dbx[jb]) / dens;
                    float uu = (dx * day[ia] - dy * dax[ia]) / dens;
                    mk[id] = (fabsf(den) > EPSI) && tt >= 0.0f && tt <= 1.0f &&
                             uu >= 0.0f && uu <= 1.0f;
                    px[id] = ax[ia] + tt * dax[ia];
                    py[id] = ay[ia] + tt * day[ia];
                }
            }
            #pragma unroll
            for (int k = 0; k < 4; k++) {
                float rx = ax[k] - bx0, ry = ay[k] - by0;
                float qx = rx * bcr + ry * bsr;
                float qy = -rx * bsr + ry * bcr;
                mk[16 + k] = (fabsf(qx) <= bdx * 0.5f + 1e-5f) &&
                             (fabsf(qy) <= bdy * 0.5f + 1e-5f);
                px[16 + k] = ax[k]; py[16 + k] = ay[k];

                rx = bx[k] - ax0; ry = by[k] - ay0;
                qx = rx * acr + ry * asr;
                qy = -rx * asr + ry * acr;
                mk[20 + k] = (fabsf(qx) <= adx * 0.5f + 1e-5f) &&
                             (fabsf(qy) <= ady * 0.5f + 1e-5f);
                px[20 + k] = bx[k]; py[20 + k] = by[k];
            }

            int cntm = 0;
            float sx = 0.0f, sy = 0.0f;
            #pragma unroll
            for (int k = 0; k < 24; k++)
                if (mk[k]) { cntm++; sx += px[k]; sy += py[k]; }
            float fc = (float)(cntm > 0 ? cntm : 1);
            float ctx = sx / fc, cty = sy / fc;

            float ang[24];
            #pragma unroll
            for (int k = 0; k < 24; k++)
                ang[k] = mk[k] ? atan2f(py[k] - cty, px[k] - ctx) : 1e9f;

            int ord[24];
            #pragma unroll
            for (int k = 0; k < 24; k++) ord[k] = k;
            for (int a2 = 1; a2 < 24; a2++) {
                int o = ord[a2];
                float key = ang[o];
                int cc = a2 - 1;
                while (cc >= 0 && ang[ord[cc]] > key) { ord[cc + 1] = ord[cc]; cc--; }
                ord[cc + 1] = o;
            }

            float fxp = px[ord[0]], fyp = py[ord[0]];
            float s2 = 0.0f;
            #pragma unroll
            for (int k = 0; k < 24; k++) {
                int o  = ord[k];
                int o2 = ord[(k + 1) % 24];
                float x0 = mk[o]  ? px[o]  : fxp;
                float y0 = mk[o]  ? py[o]  : fyp;
                float x1 = mk[o2] ? px[o2] : fxp;
                float y1 = mk[o2] ? py[o2] : fyp;
                s2 += x0 * y1 - y0 * x1;
            }
            float inter = 0.5f * fabsf(s2);
            float iou = inter / fmaxf(Aa + Ab - inter, 1e-6f);

            if (iou > THR) {
                int pos = atomicAdd(&g_pcnt[b], 1);
                if (pos < MAXP)
                    g_pairs[b * MAXP + pos] = ((unsigned)I << 10) | (unsigned)j;
            }
        }
    }
}

// ---------------------------------------------------------------------------
// k_nms: build smem bitmask from the sparse pair list, greedy NMS over
// nonzero rows only, keep-list build, output gather. Restores g_pcnt.
// ---------------------------------------------------------------------------
__global__ void __launch_bounds__(1024) k_nms(const float* __restrict__ box,
                                              const float* __restrict__ cls,
                                              float* __restrict__ out) {
    extern __shared__ unsigned int rowsSh[];   // NPRE*32 = 32768 words
    __shared__ unsigned int nzw[32];
    __shared__ int listArr[NPOST];
    __shared__ int keepTotSh;
    __shared__ int P_sh;

    int b = blockIdx.x;
    int tid = threadIdx.x;

    if (tid == 0) { P_sh = g_pcnt[b]; g_pcnt[b] = 0; }   // read + restore
    if (tid < 32) nzw[tid] = 0u;
    #pragma unroll
    for (int k = 0; k < NPRE * 32 / 1024; k++) rowsSh[tid + k * 1024] = 0u;
    __syncthreads();

    int P = P_sh; if (P > MAXP) P = MAXP;
    for (int p = tid; p < P; p += 1024) {
        unsigned v = g_pairs[b * MAXP + p];
        int i = (int)(v >> 10);
        int j = (int)(v & 1023u);
        atomicOr(&rowsSh[i * 32 + (j >> 5)], 1u << (j & 31));
        atomicOr(&nzw[i >> 5], 1u << (i & 31));
    }
    __syncthreads();

    if (tid < 32) {
        unsigned supw = 0u;
        for (int w = 0; w < 32; w++) {
            unsigned m = nzw[w];
            while (m) {
                int bit = __ffs(m) - 1; m &= m - 1;
                int i = w * 32 + bit;
                unsigned sw = __shfl_sync(0xffffffffu, supw, i >> 5);
                if (!((sw >> (i & 31)) & 1u))
                    supw |= rowsSh[i * 32 + tid];
            }
        }

        unsigned kw = ~supw;
        int c = __popc(kw);
        int pre = c;
        #pragma unroll
        for (int off = 1; off < 32; off <<= 1) {
            int v = __shfl_up_sync(0xffffffffu, pre, off);
            if (tid >= off) pre += v;
        }
        int excl = pre - c;
        if (tid == 31) keepTotSh = pre;
        unsigned mm = kw;
        int o = excl;
        while (mm && o < NPOST) {
            int bit = __ffs(mm) - 1; mm &= mm - 1;
            listArr[o++] = tid * 32 + bit;
        }
    }
    __syncthreads();

    int keepTot = keepTotSh;
    if (keepTot > NPOST) keepTot = NPOST;

    if (tid < NPOST) {
        float* rois   = out;
        float* scores = out + BATCH * NPOST * 7;
        float* labels = scores + BATCH * NPOST;
        float* logits = labels + BATCH * NPOST;
        int row = b * NPOST + tid;

        if (tid < keepTot) {
            int pos = listArr[tid];
            int sel = g_topidx[b * NPRE + pos];
            const float* bp = box + ((size_t)b * NB + sel) * 7;
            const float* lp = cls + ((size_t)b * NB + sel) * 3;
            #pragma unroll
            for (int k = 0; k < 7; k++) rois[row * 7 + k] = bp[k];
            float l0 = lp[0], l1 = lp[1], l2 = lp[2];
            logits[row * 3 + 0] = l0;
            logits[row * 3 + 1] = l1;
            logits[row * 3 + 2] = l2;
            float best = l0; int lab = 0;
            if (l1 > best) { best = l1; lab = 1; }
            if (l2 > best) { best = l2; lab = 2; }
            scores[row] = best;
            labels[row] = (float)(lab + 1);
        } else {
            #pragma unroll
            for (int k = 0; k < 7; k++) rois[row * 7 + k] = 0.0f;
            logits[row * 3 + 0] = 0.0f;
            logits[row * 3 + 1] = 0.0f;
            logits[row * 3 + 2] = 0.0f;
            scores[row] = 0.0f;
            labels[row] = 1.0f;
        }
    }
}

// ---------------------------------------------------------------------------
extern "C" void kernel_launch(void* const* d_in, const int* in_sizes, int n_in,
                              void* d_out, int out_size) {
    const float* box = (const float*)d_in[0];  // (2,16384,7)
    const float* cls = (const float*)d_in[1];  // (2,16384,3)
    float* out = (float*)d_out;

    static bool attr_set = false;
    if (!attr_set) {
        cudaFuncSetAttribute(kD, cudaFuncAttributeMaxDynamicSharedMemorySize,
                             NCAND * 8);
        cudaFuncSetAttribute(k_nms, cudaFuncAttributeMaxDynamicSharedMemorySize,
                             NPRE * 32 * 4);
        attr_set = true;
    }

    kA<<<BATCH * NB / 4 / 256, 256>>>(cls);
    kB<<<BATCH, 1024>>>();
    kC<<<BATCH * NB / 4 / 256, 256>>>();
    dim3 gd(NCAND / 256, BATCH);
    kD<<<gd, 256, NCAND * 8>>>(box);
    dim3 g((NPRE / 2) * 256 / 256, BATCH);   // 512 blocks x 256 = i[0,512) x q[0,256)
    k_iou<<<g, 256>>>();
    k_nms<<<BATCH, 1024, NPRE * 32 * 4>>>(box, cls, out);
}

// round 13
// speedup vs baseline: 1.9956x; 1.9956x over previous
#include <cuda_runtime.h>
#include <stdint.h>
#include <math.h>

#define NB    16384
#define NPRE  1024
#define NPOST 512
#define BATCH 2
#define EPSI  1e-8f
#define THR   0.8f
#define NCAND 4096
#define NBINS 16384

// ---- scratch (no device allocation allowed). All persistent state is
// restored to zero by its consumer, so graph replays see a clean slate. ----
__device__ int                g_topidx[BATCH * NPRE];
__device__ unsigned int       g_key32[BATCH * NB];     // desc-monotone score bits
__device__ unsigned int       g_hist[BATCH * NBINS];   // zeroed by kB after read
__device__ int                g_bstar[BATCH];
__device__ int                g_cnt[BATCH];            // zeroed by kB (pre-kC)
__device__ unsigned long long g_cand[BATCH * NCAND];
__device__ float4             g_bevA[BATCH * NPRE];    // {x, y, radius, area}
__device__ float4             g_bevB[BATCH * NPRE];    // {dx, dy, cos, sin}
__device__ unsigned int       g_ovl[BATCH * NPRE * 32]; // zeroed by k_nms after read

// monotone descending transform: higher score -> smaller u32
__device__ __forceinline__ unsigned desc_bits(float s) {
    unsigned u = __float_as_uint(s);
    unsigned asc = (u & 0x80000000u) ? ~u : (u | 0x80000000u);
    return ~asc;
}

// ---------------------------------------------------------------------------
// kA: keys + 14-bit histogram (whole chip). float4 loads, 4 boxes/thread.
// ---------------------------------------------------------------------------
__global__ void __launch_bounds__(256) kA(const float* __restrict__ cls) {
    int t4 = blockIdx.x * 256 + threadIdx.x;      // [0, BATCH*NB/4)
    const float4* c4 = (const float4*)cls;
    float4 f0 = c4[t4 * 3 + 0];
    float4 f1 = c4[t4 * 3 + 1];
    float4 f2 = c4[t4 * 3 + 2];
    uint4 k;
    k.x = desc_bits(fmaxf(f0.x, fmaxf(f0.y, f0.z)));
    k.y = desc_bits(fmaxf(f0.w, fmaxf(f1.x, f1.y)));
    k.z = desc_bits(fmaxf(f1.z, fmaxf(f1.w, f2.x)));
    k.w = desc_bits(fmaxf(f2.y, fmaxf(f2.z, f2.w)));
    ((uint4*)g_key32)[t4] = k;
    unsigned int* hist = g_hist + (t4 >> 12) * NBINS;   // batch = t4*4 >> 14
    atomicAdd(&hist[k.x >> 18], 1u);
    atomicAdd(&hist[k.y >> 18], 1u);
    atomicAdd(&hist[k.z >> 18], 1u);
    atomicAdd(&hist[k.w >> 18], 1u);
}

// ---------------------------------------------------------------------------
// kB: per-batch scan of 16384 bins -> b* (first bin with cum >= 1024).
// Zeroes hist bins after reading and zeroes g_cnt (restore for next replay).
// ---------------------------------------------------------------------------
__global__ void __launch_bounds__(1024) kB() {
    __shared__ unsigned int warpsum[32];
    int b = blockIdx.x;
    int tid = threadIdx.x;
    int lane = tid & 31, wid = tid >> 5;

    unsigned int* hist = g_hist + b * NBINS;
    unsigned loc[16];
    unsigned s16 = 0;
    #pragma unroll
    for (int k = 0; k < 16; k++) { loc[k] = hist[tid * 16 + k]; s16 += loc[k]; }
    #pragma unroll
    for (int k = 0; k < 16; k++) hist[tid * 16 + k] = 0u;   // restore

    unsigned p = s16;
    #pragma unroll
    for (int off = 1; off < 32; off <<= 1) {
        unsigned v = __shfl_up_sync(0xffffffffu, p, off);
        if (lane >= off) p += v;
    }
    if (lane == 31) warpsum[wid] = p;
    __syncthreads();
    if (tid < 32) {
        unsigned q = warpsum[tid];
        #pragma unroll
        for (int off = 1; off < 32; off <<= 1) {
            unsigned v = __shfl_up_sync(0xffffffffu, q, off);
            if (tid >= off) q += v;
        }
        warpsum[tid] = q;
    }
    __syncthreads();
    unsigned basePre = (wid > 0 ? warpsum[wid - 1] : 0u) + p - s16;
    if (basePre < NPRE && basePre + s16 >= NPRE) {
        unsigned run = basePre;
        #pragma unroll
        for (int k = 0; k < 16; k++) {
            unsigned c = loc[k];
            if (run < NPRE && run + c >= NPRE) { g_bstar[b] = tid * 16 + k; break; }
            run += c;
        }
    }
    if (tid == 0) g_cnt[b] = 0;
}

// ---------------------------------------------------------------------------
// kC: compact candidates (bin <= b*) into global cand. 128 blocks x 256.
// ---------------------------------------------------------------------------
__global__ void __launch_bounds__(256) kC() {
    int t = blockIdx.x * 256 + threadIdx.x;
    int b = t >> 14;
    unsigned d = g_key32[t];
    if ((int)(d >> 18) <= g_bstar[b]) {
        int pos = atomicAdd(&g_cnt[b], 1);
        if (pos < NCAND)
            g_cand[b * NCAND + pos] =
                (((unsigned long long)d) << 32) | (unsigned)(t & (NB - 1));
    }
}

// ---------------------------------------------------------------------------
// kD: exact rank-by-counting (keys unique) + scatter of top-1024 with
// per-box bev precompute. grid (16, BATCH) x 256; cands staged in smem.
// ---------------------------------------------------------------------------
__global__ void __launch_bounds__(256) kD(const float* __restrict__ box) {
    extern __shared__ unsigned long long sh[];    // NCAND u64 (32KB)
    int b = blockIdx.y;
    int tid = threadIdx.x;
    int C = g_cnt[b];
    if (C > NCAND) C = NCAND;
    int me = blockIdx.x * 256 + tid;
    if (blockIdx.x * 256 >= C) return;            // whole block idle

    const unsigned long long* cand = g_cand + b * NCAND;
    for (int i = tid; i < C; i += 256) sh[i] = cand[i];
    __syncthreads();

    if (me >= C) return;
    unsigned long long my = sh[me];
    int rank = 0;
    int j = 0;
    for (; j + 4 <= C; j += 4) {
        rank += (sh[j]     < my);
        rank += (sh[j + 1] < my);
        rank += (sh[j + 2] < my);
        rank += (sh[j + 3] < my);
    }
    for (; j < C; j++) rank += (sh[j] < my);

    if (rank < NPRE) {
        int idx = (int)(my & 0xffffffffu);
        g_topidx[b * NPRE + rank] = idx;
        const float* bp = box + ((size_t)b * NB + idx) * 7;
        float x = bp[0], y = bp[1], dx = bp[3], dy = bp[4], ry = bp[6];
        float r = 0.5f * sqrtf(dx * dx + dy * dy);
        g_bevA[b * NPRE + rank] = make_float4(x, y, r, dx * dy);
        g_bevB[b * NPRE + rank] = make_float4(dx, dy, cosf(ry), sinf(ry));
    }
}

// ---------------------------------------------------------------------------
// k_iou: pairwise rotated-BEV IoU > 0.8 -> bitmask. Triangular fold,
// float4 quick rejects, exact reference polygon algorithm for survivors.
// ---------------------------------------------------------------------------
__global__ void __launch_bounds__(256) k_iou() {
    int t = blockIdx.x * 256 + threadIdx.x;
    int b = blockIdx.y;
    int i = t >> 10;          // [0, 512)
    int j = t & (NPRE - 1);
    if (j <= i) {             // fold onto upper triangle
        i = NPRE - 1 - i;
        j = NPRE - 1 - j;
        if (j <= i) return;   // diagonal
    }

    float4 A4 = g_bevA[b * NPRE + i];
    float4 B4 = g_bevA[b * NPRE + j];

    float ddx = B4.x - A4.x, ddy = B4.y - A4.y;
    float rr = A4.z + B4.z;
    if (ddx * ddx + ddy * ddy > rr * rr) return;

    float Aa = A4.w, Ab = B4.w;
    float mn = fminf(Aa, Ab), mx = fmaxf(Aa, Ab);
    if (mn <= 0.79f * mx) return;

    float4 Ad = g_bevB[b * NPRE + i];
    float4 Bd = g_bevB[b * NPRE + j];
    float ax0 = A4.x, ay0 = A4.y, adx = Ad.x, ady = Ad.y, acr = Ad.z, asr = Ad.w;
    float bx0 = B4.x, by0 = B4.y, bdx = Bd.x, bdy = Bd.y, bcr = Bd.z, bsr = Bd.w;

    const float offx[4] = { 0.5f, -0.5f, -0.5f,  0.5f };
    const float offy[4] = { 0.5f,  0.5f, -0.5f, -0.5f };

    float ax[4], ay[4], bx[4], by[4];
#pragma unroll
    for (int k = 0; k < 4; k++) {
        float lx = adx * offx[k], ly = ady * offy[k];
        ax[k] = ax0 + lx * acr - ly * asr;
        ay[k] = ay0 + lx * asr + ly * acr;
        lx = bdx * offx[k]; ly = bdy * offy[k];
        bx[k] = bx0 + lx * bcr - ly * bsr;
        by[k] = by0 + lx * bsr + ly * bcr;
    }
    float dax[4], day[4], dbx[4], dby[4];
#pragma unroll
    for (int k = 0; k < 4; k++) {
        dax[k] = ax[(k + 1) & 3] - ax[k];
        day[k] = ay[(k + 1) & 3] - ay[k];
        dbx[k] = bx[(k + 1) & 3] - bx[k];
        dby[k] = by[(k + 1) & 3] - by[k];
    }

    float px[24], py[24];
    bool  mk[24];
#pragma unroll
    for (int ia = 0; ia < 4; ia++) {
#pragma unroll
        for (int jb = 0; jb < 4; jb++) {
            int id = ia * 4 + jb;
            float den = dax[ia] * dby[jb] - day[ia] * dbx[jb];
            float dx = bx[jb] - ax[ia], dy = by[jb] - ay[ia];
            float dens = (fabsf(den) > EPSI) ? den : 1.0f;
            float tt = (dx * dby[jb] - dy * dbx[jb]) / dens;
            float uu = (dx * day[ia] - dy * dax[ia]) / dens;
            mk[id] = (fabsf(den) > EPSI) && tt >= 0.0f && tt <= 1.0f &&
                     uu >= 0.0f && uu <= 1.0f;
            px[id] = ax[ia] + tt * dax[ia];
            py[id] = ay[ia] + tt * day[ia];
        }
    }
#pragma unroll
    for (int k = 0; k < 4; k++) {
        float rx = ax[k] - bx0, ry = ay[k] - by0;
        float qx = rx * bcr + ry * bsr;
        float qy = -rx * bsr + ry * bcr;
        mk[16 + k] = (fabsf(qx) <= bdx * 0.5f + 1e-5f) &&
                     (fabsf(qy) <= bdy * 0.5f + 1e-5f);
        px[16 + k] = ax[k]; py[16 + k] = ay[k];

        rx = bx[k] - ax0; ry = by[k] - ay0;
        qx = rx * acr + ry * asr;
        qy = -rx * asr + ry * acr;
        mk[20 + k] = (fabsf(qx) <= adx * 0.5f + 1e-5f) &&
                     (fabsf(qy) <= ady * 0.5f + 1e-5f);
        px[20 + k] = bx[k]; py[20 + k] = by[k];
    }

    int cntm = 0;
    float sx = 0.0f, sy = 0.0f;
#pragma unroll
    for (int k = 0; k < 24; k++)
        if (mk[k]) { cntm++; sx += px[k]; sy += py[k]; }
    float fc = (float)(cntm > 0 ? cntm : 1);
    float ctx = sx / fc, cty = sy / fc;

    float ang[24];
#pragma unroll
    for (int k = 0; k < 24; k++)
        ang[k] = mk[k] ? atan2f(py[k] - cty, px[k] - ctx) : 1e9f;

    int ord[24];
#pragma unroll
    for (int k = 0; k < 24; k++) ord[k] = k;
    for (int a2 = 1; a2 < 24; a2++) {
        int o = ord[a2];
        float key = ang[o];
        int c = a2 - 1;
        while (c >= 0 && ang[ord[c]] > key) { ord[c + 1] = ord[c]; c--; }
        ord[c + 1] = o;
    }

    float fxp = px[ord[0]], fyp = py[ord[0]];
    float s2 = 0.0f;
#pragma unroll
    for (int k = 0; k < 24; k++) {
        int o  = ord[k];
        int o2 = ord[(k + 1) % 24];
        float x0 = mk[o]  ? px[o]  : fxp;
        float y0 = mk[o]  ? py[o]  : fyp;
        float x1 = mk[o2] ? px[o2] : fxp;
        float y1 = mk[o2] ? py[o2] : fyp;
        s2 += x0 * y1 - y0 * x1;
    }
    float inter = 0.5f * fabsf(s2);
    float iou = inter / fmaxf(Aa + Ab - inter, 1e-6f);

    if (iou > THR)
        atomicOr(&g_ovl[(b * NPRE + i) * 32 + (j >> 5)], 1u << (j & 31));
}

// ---------------------------------------------------------------------------
// k_nms: greedy NMS over nonzero rows only (matrix staged in smem; global
// copy restored to zero for next replay), keep-list build, output gather.
// ---------------------------------------------------------------------------
__global__ void __launch_bounds__(1024) k_nms(const float* __restrict__ box,
                                              const float* __restrict__ cls,
                                              float* __restrict__ out) {
    extern __shared__ unsigned int rowsSh[];   // NPRE*32 = 32768 words
    __shared__ unsigned int nzw[32];
    __shared__ int listArr[NPOST];
    __shared__ int keepTotSh;

    int b = blockIdx.x;
    int tid = threadIdx.x;

    if (tid < 32) nzw[tid] = 0u;
    __syncthreads();

    unsigned int* base = g_ovl + b * NPRE * 32;
    #pragma unroll
    for (int k = 0; k < NPRE * 32 / 1024; k++) {
        int idx = tid + k * 1024;
        unsigned v = base[idx];
        rowsSh[idx] = v;
        if (v) {
            base[idx] = 0u;                       // restore for next replay
            int row = idx >> 5;
            atomicOr(&nzw[row >> 5], 1u << (row & 31));
        }
    }
    __syncthreads();

    if (tid < 32) {
        unsigned supw = 0u;
        for (int w = 0; w < 32; w++) {
            unsigned m = nzw[w];
            while (m) {
                int bit = __ffs(m) - 1; m &= m - 1;
                int i = w * 32 + bit;
                unsigned sw = __shfl_sync(0xffffffffu, supw, i >> 5);
                if (!((sw >> (i & 31)) & 1u))
                    supw |= rowsSh[i * 32 + tid];
            }
        }

        unsigned kw = ~supw;
        int c = __popc(kw);
        int pre = c;
        #pragma unroll
        for (int off = 1; off < 32; off <<= 1) {
            int v = __shfl_up_sync(0xffffffffu, pre, off);
            if (tid >= off) pre += v;
        }
        int excl = pre - c;
        if (tid == 31) keepTotSh = pre;
        unsigned mm = kw;
        int o = excl;
        while (mm && o < NPOST) {
            int bit = __ffs(mm) - 1; mm &= mm - 1;
            listArr[o++] = tid * 32 + bit;
        }
    }
    __syncthreads();

    int keepTot = keepTotSh;
    if (keepTot > NPOST) keepTot = NPOST;

    if (tid < NPOST) {
        float* rois   = out;
        float* scores = out + BATCH * NPOST * 7;
        float* labels = scores + BATCH * NPOST;
        float* logits = labels + BATCH * NPOST;
        int row = b * NPOST + tid;

        if (tid < keepTot) {
            int pos = listArr[tid];
            int sel = g_topidx[b * NPRE + pos];
            const float* bp = box + ((size_t)b * NB + sel) * 7;
            const float* lp = cls + ((size_t)b * NB + sel) * 3;
            #pragma unroll
            for (int k = 0; k < 7; k++) rois[row * 7 + k] = bp[k];
            float l0 = lp[0], l1 = lp[1], l2 = lp[2];
            logits[row * 3 + 0] = l0;
            logits[row * 3 + 1] = l1;
            logits[row * 3 + 2] = l2;
            float best = l0; int lab = 0;
            if (l1 > best) { best = l1; lab = 1; }
            if (l2 > best) { best = l2; lab = 2; }
            scores[row] = best;
            labels[row] = (float)(lab + 1);
        } else {
            #pragma unroll
            for (int k = 0; k < 7; k++) rois[row * 7 + k] = 0.0f;
            logits[row * 3 + 0] = 0.0f;
            logits[row * 3 + 1] = 0.0f;
            logits[row * 3 + 2] = 0.0f;
            scores[row] = 0.0f;
            labels[row] = 1.0f;
        }
    }
}

// ---------------------------------------------------------------------------
extern "C" void kernel_launch(void* const* d_in, const int* in_sizes, int n_in,
                              void* d_out, int out_size) {
    const float* box = (const float*)d_in[0];  // (2,16384,7)
    const float* cls = (const float*)d_in[1];  // (2,16384,3)
    float* out = (float*)d_out;

    static bool attr_set = false;
    if (!attr_set) {
        cudaFuncSetAttribute(kD, cudaFuncAttributeMaxDynamicSharedMemorySize,
                             NCAND * 8);
        cudaFuncSetAttribute(k_nms, cudaFuncAttributeMaxDynamicSharedMemorySize,
                             NPRE * 32 * 4);
        attr_set = true;
    }

    kA<<<BATCH * NB / 4 / 256, 256>>>(cls);
    kB<<<BATCH, 1024>>>();
    kC<<<BATCH * NB / 256, 256>>>();
    dim3 gd(NCAND / 256, BATCH);
    kD<<<gd, 256, NCAND * 8>>>(box);
    dim3 g((NPRE / 2 * NPRE) / 256, BATCH);
    k_iou<<<g, 256>>>();
    k_nms<<<BATCH, 1024, NPRE * 32 * 4>>>(box, cls, out);
}

// round 14
// speedup vs baseline: 2.1832x; 1.0940x over previous
#include <cuda_runtime.h>
#include <stdint.h>
#include <math.h>

#define NB    16384
#define NPRE  1024
#define NPOST 512
#define BATCH 2
#define EPSI  1e-8f
#define THR   0.8f
#define NCAND 4096
#define NBINS 16384

// ---- scratch (no device allocation allowed). All persistent state is
// restored to zero by its consumer, so graph replays see a clean slate. ----
__device__ int                g_topidx[BATCH * NPRE];
__device__ unsigned int       g_key32[BATCH * NB];     // desc-monotone score bits
__device__ unsigned int       g_hist[BATCH * NBINS];   // zeroed by kB after read
__device__ int                g_bstar[BATCH];
__device__ int                g_cnt[BATCH];            // zeroed by kB (pre-kC)
__device__ unsigned long long g_cand[BATCH * NCAND];
__device__ float4             g_bevA[BATCH * NPRE];    // {x, y, radius, area}
__device__ float4             g_bevB[BATCH * NPRE];    // {dx, dy, cos, sin}
__device__ unsigned int       g_ovl[BATCH * NPRE * 32]; // zeroed by k_nms after read

// monotone descending transform: higher score -> smaller u32
__device__ __forceinline__ unsigned desc_bits(float s) {
    unsigned u = __float_as_uint(s);
    unsigned asc = (u & 0x80000000u) ? ~u : (u | 0x80000000u);
    return ~asc;
}

// ---------------------------------------------------------------------------
// kA: keys + 14-bit histogram (whole chip). float4 loads, 4 boxes/thread.
// ---------------------------------------------------------------------------
__global__ void __launch_bounds__(256) kA(const float* __restrict__ cls) {
    int t4 = blockIdx.x * 256 + threadIdx.x;      // [0, BATCH*NB/4)
    const float4* c4 = (const float4*)cls;
    float4 f0 = c4[t4 * 3 + 0];
    float4 f1 = c4[t4 * 3 + 1];
    float4 f2 = c4[t4 * 3 + 2];
    uint4 k;
    k.x = desc_bits(fmaxf(f0.x, fmaxf(f0.y, f0.z)));
    k.y = desc_bits(fmaxf(f0.w, fmaxf(f1.x, f1.y)));
    k.z = desc_bits(fmaxf(f1.z, fmaxf(f1.w, f2.x)));
    k.w = desc_bits(fmaxf(f2.y, fmaxf(f2.z, f2.w)));
    ((uint4*)g_key32)[t4] = k;
    unsigned int* hist = g_hist + (t4 >> 12) * NBINS;   // batch = t4*4 >> 14
    atomicAdd(&hist[k.x >> 18], 1u);
    atomicAdd(&hist[k.y >> 18], 1u);
    atomicAdd(&hist[k.z >> 18], 1u);
    atomicAdd(&hist[k.w >> 18], 1u);
}

// ---------------------------------------------------------------------------
// kB: per-batch scan of 16384 bins -> b* (first bin with cum >= 1024).
// Zeroes hist bins after reading and zeroes g_cnt (restore for next replay).
// ---------------------------------------------------------------------------
__global__ void __launch_bounds__(1024) kB() {
    __shared__ unsigned int warpsum[32];
    int b = blockIdx.x;
    int tid = threadIdx.x;
    int lane = tid & 31, wid = tid >> 5;

    unsigned int* hist = g_hist + b * NBINS;
    unsigned loc[16];
    unsigned s16 = 0;
    #pragma unroll
    for (int k = 0; k < 16; k++) { loc[k] = hist[tid * 16 + k]; s16 += loc[k]; }
    #pragma unroll
    for (int k = 0; k < 16; k++) hist[tid * 16 + k] = 0u;   // restore

    unsigned p = s16;
    #pragma unroll
    for (int off = 1; off < 32; off <<= 1) {
        unsigned v = __shfl_up_sync(0xffffffffu, p, off);
        if (lane >= off) p += v;
    }
    if (lane == 31) warpsum[wid] = p;
    __syncthreads();
    if (tid < 32) {
        unsigned q = warpsum[tid];
        #pragma unroll
        for (int off = 1; off < 32; off <<= 1) {
            unsigned v = __shfl_up_sync(0xffffffffu, q, off);
            if (tid >= off) q += v;
        }
        warpsum[tid] = q;
    }
    __syncthreads();
    unsigned basePre = (wid > 0 ? warpsum[wid - 1] : 0u) + p - s16;
    if (basePre < NPRE && basePre + s16 >= NPRE) {
        unsigned run = basePre;
        #pragma unroll
        for (int k = 0; k < 16; k++) {
            unsigned c = loc[k];
            if (run < NPRE && run + c >= NPRE) { g_bstar[b] = tid * 16 + k; break; }
            run += c;
        }
    }
    if (tid == 0) g_cnt[b] = 0;
}

// ---------------------------------------------------------------------------
// kC: compact candidates (bin <= b*) into global cand. 128 blocks x 256.
// ---------------------------------------------------------------------------
__global__ void __launch_bounds__(256) kC() {
    int t = blockIdx.x * 256 + threadIdx.x;
    int b = t >> 14;
    unsigned d = g_key32[t];
    if ((int)(d >> 18) <= g_bstar[b]) {
        int pos = atomicAdd(&g_cnt[b], 1);
        if (pos < NCAND)
            g_cand[b * NCAND + pos] =
                (((unsigned long long)d) << 32) | (unsigned)(t & (NB - 1));
    }
}

// ---------------------------------------------------------------------------
// kD: warp-per-candidate exact rank-by-counting. Block owns 8 candidates
// (one per warp); 32 lanes stride the staged array and reduce. Blocks with
// no candidates exit before staging. Scatter + bev precompute as before.
// ---------------------------------------------------------------------------
__global__ void __launch_bounds__(256) kD(const float* __restrict__ box) {
    extern __shared__ unsigned long long sh[];    // up to NCAND u64 (32KB)
    int b = blockIdx.y;
    int tid = threadIdx.x;
    int lane = tid & 31, w = tid >> 5;
    int C = g_cnt[b];
    if (C > NCAND) C = NCAND;
    if (blockIdx.x * 8 >= C) return;              // whole block idle

    const unsigned long long* cand = g_cand + b * NCAND;
    for (int i = tid; i < C; i += 256) sh[i] = cand[i];
    __syncthreads();

    int me = blockIdx.x * 8 + w;                  // this warp's candidate
    if (me >= C) return;
    unsigned long long my = sh[me];

    int cnt = 0;
    for (int j = lane; j < C; j += 32) cnt += (sh[j] < my);
    int rank = __reduce_add_sync(0xffffffffu, cnt);

    if (lane == 0 && rank < NPRE) {
        int idx = (int)(my & 0xffffffffu);
        g_topidx[b * NPRE + rank] = idx;
        const float* bp = box + ((size_t)b * NB + idx) * 7;
        float x = bp[0], y = bp[1], dx = bp[3], dy = bp[4], ry = bp[6];
        float r = 0.5f * sqrtf(dx * dx + dy * dy);
        g_bevA[b * NPRE + rank] = make_float4(x, y, r, dx * dy);
        g_bevB[b * NPRE + rank] = make_float4(dx, dy, cosf(ry), sinf(ry));
    }
}

// ---------------------------------------------------------------------------
// k_iou: pairwise rotated-BEV IoU > 0.8 -> bitmask. Triangular fold,
// float4 quick rejects, exact reference polygon algorithm for survivors.
// ---------------------------------------------------------------------------
__global__ void __launch_bounds__(256) k_iou() {
    int t = blockIdx.x * 256 + threadIdx.x;
    int b = blockIdx.y;
    int i = t >> 10;          // [0, 512)
    int j = t & (NPRE - 1);
    if (j <= i) {             // fold onto upper triangle
        i = NPRE - 1 - i;
        j = NPRE - 1 - j;
        if (j <= i) return;   // diagonal
    }

    float4 A4 = g_bevA[b * NPRE + i];
    float4 B4 = g_bevA[b * NPRE + j];

    float ddx = B4.x - A4.x, ddy = B4.y - A4.y;
    float rr = A4.z + B4.z;
    if (ddx * ddx + ddy * ddy > rr * rr) return;

    float Aa = A4.w, Ab = B4.w;
    float mn = fminf(Aa, Ab), mx = fmaxf(Aa, Ab);
    if (mn <= 0.79f * mx) return;

    float4 Ad = g_bevB[b * NPRE + i];
    float4 Bd = g_bevB[b * NPRE + j];
    float ax0 = A4.x, ay0 = A4.y, adx = Ad.x, ady = Ad.y, acr = Ad.z, asr = Ad.w;
    float bx0 = B4.x, by0 = B4.y, bdx = Bd.x, bdy = Bd.y, bcr = Bd.z, bsr = Bd.w;

    const float offx[4] = { 0.5f, -0.5f, -0.5f,  0.5f };
    const float offy[4] = { 0.5f,  0.5f, -0.5f, -0.5f };

    float ax[4], ay[4], bx[4], by[4];
#pragma unroll
    for (int k = 0; k < 4; k++) {
        float lx = adx * offx[k], ly = ady * offy[k];
        ax[k] = ax0 + lx * acr - ly * asr;
        ay[k] = ay0 + lx * asr + ly * acr;
        lx = bdx * offx[k]; ly = bdy * offy[k];
        bx[k] = bx0 + lx * bcr - ly * bsr;
        by[k] = by0 + lx * bsr + ly * bcr;
    }
    float dax[4], day[4], dbx[4], dby[4];
#pragma unroll
    for (int k = 0; k < 4; k++) {
        dax[k] = ax[(k + 1) & 3] - ax[k];
        day[k] = ay[(k + 1) & 3] - ay[k];
        dbx[k] = bx[(k + 1) & 3] - bx[k];
        dby[k] = by[(k + 1) & 3] - by[k];
    }

    float px[24], py[24];
    bool  mk[24];
#pragma unroll
    for (int ia = 0; ia < 4; ia++) {
#pragma unroll
        for (int jb = 0; jb < 4; jb++) {
            int id = ia * 4 + jb;
            float den = dax[ia] * dby[jb] - day[ia] * dbx[jb];
            float dx = bx[jb] - ax[ia], dy = by[jb] - ay[ia];
            float dens = (fabsf(den) > EPSI) ? den : 1.0f;
            float tt = (dx * dby[jb] - dy * dbx[jb]) / dens;
            float uu = (dx * day[ia] - dy * dax[ia]) / dens;
            mk[id] = (fabsf(den) > EPSI) && tt >= 0.0f && tt <= 1.0f &&
                     uu >= 0.0f && uu <= 1.0f;
            px[id] = ax[ia] + tt * dax[ia];
            py[id] = ay[ia] + tt * day[ia];
        }
    }
#pragma unroll
    for (int k = 0; k < 4; k++) {
        float rx = ax[k] - bx0, ry = ay[k] - by0;
        float qx = rx * bcr + ry * bsr;
        float qy = -rx * bsr + ry * bcr;
        mk[16 + k] = (fabsf(qx) <= bdx * 0.5f + 1e-5f) &&
                     (fabsf(qy) <= bdy * 0.5f + 1e-5f);
        px[16 + k] = ax[k]; py[16 + k] = ay[k];

        rx = bx[k] - ax0; ry = by[k] - ay0;
        qx = rx * acr + ry * asr;
        qy = -rx * asr + ry * acr;
        mk[20 + k] = (fabsf(qx) <= adx * 0.5f + 1e-5f) &&
                     (fabsf(qy) <= ady * 0.5f + 1e-5f);
        px[20 + k] = bx[k]; py[20 + k] = by[k];
    }

    int cntm = 0;
    float sx = 0.0f, sy = 0.0f;
#pragma unroll
    for (int k = 0; k < 24; k++)
        if (mk[k]) { cntm++; sx += px[k]; sy += py[k]; }
    float fc = (float)(cntm > 0 ? cntm : 1);
    float ctx = sx / fc, cty = sy / fc;

    float ang[24];
#pragma unroll
    for (int k = 0; k < 24; k++)
        ang[k] = mk[k] ? atan2f(py[k] - cty, px[k] - ctx) : 1e9f;

    int ord[24];
#pragma unroll
    for (int k = 0; k < 24; k++) ord[k] = k;
    for (int a2 = 1; a2 < 24; a2++) {
        int o = ord[a2];
        float key = ang[o];
        int c = a2 - 1;
        while (c >= 0 && ang[ord[c]] > key) { ord[c + 1] = ord[c]; c--; }
        ord[c + 1] = o;
    }

    float fxp = px[ord[0]], fyp = py[ord[0]];
    float s2 = 0.0f;
#pragma unroll
    for (int k = 0; k < 24; k++) {
        int o  = ord[k];
        int o2 = ord[(k + 1) % 24];
        float x0 = mk[o]  ? px[o]  : fxp;
        float y0 = mk[o]  ? py[o]  : fyp;
        float x1 = mk[o2] ? px[o2] : fxp;
        float y1 = mk[o2] ? py[o2] : fyp;
        s2 += x0 * y1 - y0 * x1;
    }
    float inter = 0.5f * fabsf(s2);
    float iou = inter / fmaxf(Aa + Ab - inter, 1e-6f);

    if (iou > THR)
        atomicOr(&g_ovl[(b * NPRE + i) * 32 + (j >> 5)], 1u << (j & 31));
}

// ---------------------------------------------------------------------------
// k_nms: greedy NMS over nonzero rows only (matrix staged in smem; global
// copy restored to zero for next replay), keep-list build, output gather.
// ---------------------------------------------------------------------------
__global__ void __launch_bounds__(1024) k_nms(const float* __restrict__ box,
                                              const float* __restrict__ cls,
                                              float* __restrict__ out) {
    extern __shared__ unsigned int rowsSh[];   // NPRE*32 = 32768 words
    __shared__ unsigned int nzw[32];
    __shared__ int listArr[NPOST];
    __shared__ int keepTotSh;

    int b = blockIdx.x;
    int tid = threadIdx.x;

    if (tid < 32) nzw[tid] = 0u;
    __syncthreads();

    unsigned int* base = g_ovl + b * NPRE * 32;
    #pragma unroll
    for (int k = 0; k < NPRE * 32 / 1024; k++) {
        int idx = tid + k * 1024;
        unsigned v = base[idx];
        rowsSh[idx] = v;
        if (v) {
            base[idx] = 0u;                       // restore for next replay
            int row = idx >> 5;
            atomicOr(&nzw[row >> 5], 1u << (row & 31));
        }
    }
    __syncthreads();

    if (tid < 32) {
        unsigned supw = 0u;
        for (int w = 0; w < 32; w++) {
            unsigned m = nzw[w];
            while (m) {
                int bit = __ffs(m) - 1; m &= m - 1;
                int i = w * 32 + bit;
                unsigned sw = __shfl_sync(0xffffffffu, supw, i >> 5);
                if (!((sw >> (i & 31)) & 1u))
                    supw |= rowsSh[i * 32 + tid];
            }
        }

        unsigned kw = ~supw;
        int c = __popc(kw);
        int pre = c;
        #pragma unroll
        for (int off = 1; off < 32; off <<= 1) {
            int v = __shfl_up_sync(0xffffffffu, pre, off);
            if (tid >= off) pre += v;
        }
        int excl = pre - c;
        if (tid == 31) keepTotSh = pre;
        unsigned mm = kw;
        int o = excl;
        while (mm && o < NPOST) {
            int bit = __ffs(mm) - 1; mm &= mm - 1;
            listArr[o++] = tid * 32 + bit;
        }
    }
    __syncthreads();

    int keepTot = keepTotSh;
    if (keepTot > NPOST) keepTot = NPOST;

    if (tid < NPOST) {
        float* rois   = out;
        float* scores = out + BATCH * NPOST * 7;
        float* labels = scores + BATCH * NPOST;
        float* logits = labels + BATCH * NPOST;
        int row = b * NPOST + tid;

        if (tid < keepTot) {
            int pos = listArr[tid];
            int sel = g_topidx[b * NPRE + pos];
            const float* bp = box + ((size_t)b * NB + sel) * 7;
            const float* lp = cls + ((size_t)b * NB + sel) * 3;
            #pragma unroll
            for (int k = 0; k < 7; k++) rois[row * 7 + k] = bp[k];
            float l0 = lp[0], l1 = lp[1], l2 = lp[2];
            logits[row * 3 + 0] = l0;
            logits[row * 3 + 1] = l1;
            logits[row * 3 + 2] = l2;
            float best = l0; int lab = 0;
            if (l1 > best) { best = l1; lab = 1; }
            if (l2 > best) { best = l2; lab = 2; }
            scores[row] = best;
            labels[row] = (float)(lab + 1);
        } else {
            #pragma unroll
            for (int k = 0; k < 7; k++) rois[row * 7 + k] = 0.0f;
            logits[row * 3 + 0] = 0.0f;
            logits[row * 3 + 1] = 0.0f;
            logits[row * 3 + 2] = 0.0f;
            scores[row] = 0.0f;
            labels[row] = 1.0f;
        }
    }
}

// ---------------------------------------------------------------------------
extern "C" void kernel_launch(void* const* d_in, const int* in_sizes, int n_in,
                              void* d_out, int out_size) {
    const float* box = (const float*)d_in[0];  // (2,16384,7)
    const float* cls = (const float*)d_in[1];  // (2,16384,3)
    float* out = (float*)d_out;

    static bool attr_set = false;
    if (!attr_set) {
        cudaFuncSetAttribute(kD, cudaFuncAttributeMaxDynamicSharedMemorySize,
                             NCAND * 8);
        cudaFuncSetAttribute(k_nms, cudaFuncAttributeMaxDynamicSharedMemorySize,
                             NPRE * 32 * 4);
        attr_set = true;
    }

    kA<<<BATCH * NB / 4 / 256, 256>>>(cls);
    kB<<<BATCH, 1024>>>();
    kC<<<BATCH * NB / 256, 256>>>();
    dim3 gd(NCAND / 8, BATCH);                 // warp-per-candidate
    kD<<<gd, 256, NCAND * 8>>>(box);
    dim3 g((NPRE / 2 * NPRE) / 256, BATCH);
    k_iou<<<g, 256>>>();
    k_nms<<<BATCH, 1024, NPRE * 32 * 4>>>(box, cls, out);
}